// round 1
// baseline (speedup 1.0000x reference)
#include <cuda_runtime.h>

#define N_NODES  100000
#define N_EDGES  3200000
#define N_GRAPHS 128

// ---------------- scratch (device globals: no allocations allowed) ----------
__device__ float g_h1[N_NODES * 64];   // X @ W1
__device__ float g_o1[N_NODES * 64];   // aggregated layer 1 (pre-bias/relu)
__device__ float g_h2[N_NODES * 32];   // relu(o1+b1) @ W2
__device__ float g_o2[N_NODES * 32];   // aggregated layer 2 (pre-bias/relu)
__device__ float g_dinv[N_NODES];
__device__ int   g_deg[N_NODES];
__device__ float g_pool[N_GRAPHS * 32];

// ---------------- degree / norm ---------------------------------------------
__global__ void deg_init_kernel() {
    int i = blockIdx.x * blockDim.x + threadIdx.x;
    if (i < N_NODES) g_deg[i] = 1;                    // self loop
}

__global__ void deg_count_kernel(const int* __restrict__ ei) {
    int e = blockIdx.x * blockDim.x + threadIdx.x;
    if (e < N_EDGES) atomicAdd(&g_deg[ei[N_EDGES + e]], 1);
}

__global__ void dinv_kernel() {
    int i = blockIdx.x * blockDim.x + threadIdx.x;
    if (i < N_NODES) g_dinv[i] = rsqrtf((float)g_deg[i]);
}

// ---------------- GEMM 1: h1 = x @ W1   (100000x47 @ 47x64) -----------------
// 256 threads/block: 32 rows x 8 threads, each thread 8 output cols.
__global__ void xw1_kernel(const float* __restrict__ x, const float* __restrict__ W1) {
    __shared__ float sW[47 * 64];
    int tid = threadIdx.x;
    for (int i = tid; i < 47 * 64; i += 256) sW[i] = W1[i];
    __syncthreads();

    int row = blockIdx.x * 32 + (tid >> 3);
    int cg  = (tid & 7) * 8;
    if (row >= N_NODES) return;

    float acc[8] = {0.f, 0.f, 0.f, 0.f, 0.f, 0.f, 0.f, 0.f};
    const float* xr = x + (long long)row * 47;
#pragma unroll
    for (int k = 0; k < 47; k++) {
        float xv = __ldg(xr + k);
#pragma unroll
        for (int j = 0; j < 8; j++) acc[j] += xv * sW[k * 64 + cg + j];
    }
    float4* o = (float4*)(g_h1 + (long long)row * 64 + cg);
    o[0] = make_float4(acc[0], acc[1], acc[2], acc[3]);
    o[1] = make_float4(acc[4], acc[5], acc[6], acc[7]);
}

// ---------------- GEMM 2: h2 = relu(o1 + b1) @ W2   (100000x64 @ 64x32) -----
// 256 threads/block: 32 rows x 8 threads, each thread 4 output cols.
__global__ void xw2_kernel(const float* __restrict__ W2, const float* __restrict__ b1) {
    __shared__ float sW[64 * 32];
    __shared__ float sb[64];
    int tid = threadIdx.x;
    for (int i = tid; i < 64 * 32; i += 256) sW[i] = W2[i];
    if (tid < 64) sb[tid] = b1[tid];
    __syncthreads();

    int row = blockIdx.x * 32 + (tid >> 3);
    int cg  = (tid & 7) * 4;
    if (row >= N_NODES) return;

    float acc[4] = {0.f, 0.f, 0.f, 0.f};
    const float* ir = g_o1 + (long long)row * 64;
#pragma unroll
    for (int k = 0; k < 64; k++) {
        float v = fmaxf(ir[k] + sb[k], 0.f);
#pragma unroll
        for (int j = 0; j < 4; j++) acc[j] += v * sW[k * 32 + cg + j];
    }
    *(float4*)(g_h2 + (long long)row * 32 + cg) =
        make_float4(acc[0], acc[1], acc[2], acc[3]);
}

// ---------------- output init with fused self-loop: o = h * dinv^2 ----------
template <int F4, int LOG2F4>   // F4 = floats/4 per node (16 or 8)
__global__ void selfloop_init_kernel(const float* __restrict__ h, float* __restrict__ o) {
    unsigned t = blockIdx.x * blockDim.x + threadIdx.x;
    if (t >= (unsigned)N_NODES * F4) return;
    unsigned node = t >> LOG2F4;
    float d = g_dinv[node];
    float s = d * d;
    float4 v = ((const float4*)h)[t];
    ((float4*)o)[t] = make_float4(v.x * s, v.y * s, v.z * s, v.w * s);
}

// ---------------- edge scatter: o[dst] += h[src] * dinv[src]*dinv[dst] ------
// F4 threads per edge, one float4 + one red.global.add.v4.f32 each.
template <int F4, int LOG2F4>
__global__ void scatter_kernel(const int* __restrict__ ei,
                               const float* __restrict__ h,
                               float* __restrict__ o) {
    unsigned t = blockIdx.x * blockDim.x + threadIdx.x;
    if (t >= (unsigned)N_EDGES * F4) return;
    unsigned e = t >> LOG2F4;
    unsigned p = t & (F4 - 1);
    int src = __ldg(ei + e);
    int dst = __ldg(ei + N_EDGES + e);
    float norm = g_dinv[src] * g_dinv[dst];
    float4 v = ((const float4*)(h + (long long)src * (F4 * 4)))[p];
    float4 m = make_float4(v.x * norm, v.y * norm, v.z * norm, v.w * norm);
    float* addr = o + (long long)dst * (F4 * 4) + p * 4;
    asm volatile("red.global.add.v4.f32 [%0], {%1,%2,%3,%4};"
                 :: "l"(addr), "f"(m.x), "f"(m.y), "f"(m.z), "f"(m.w)
                 : "memory");
}

// ---------------- pooling: g[batch[n]] += relu(o2[n] + b2) ------------------
__global__ void pool_zero_kernel() {
    int i = blockIdx.x * blockDim.x + threadIdx.x;
    if (i < N_GRAPHS * 32) g_pool[i] = 0.f;
}

// batch is sorted: each thread owns one feature column over a 32-node run and
// flushes a single atomic per (run, graph-id change).
__global__ void pool_kernel(const int* __restrict__ batch, const float* __restrict__ b2) {
    unsigned t = blockIdx.x * blockDim.x + threadIdx.x;
    int col   = t & 31;
    int chunk = t >> 5;
    int n0 = chunk * 32;
    if (n0 >= N_NODES) return;
    int n1 = min(n0 + 32, N_NODES);
    float bias = __ldg(b2 + col);
    float acc = 0.f;
    int cur = __ldg(batch + n0);
    for (int n = n0; n < n1; n++) {
        int b = __ldg(batch + n);
        if (b != cur) {
            atomicAdd(&g_pool[cur * 32 + col], acc);
            acc = 0.f;
            cur = b;
        }
        acc += fmaxf(g_o2[(long long)n * 32 + col] + bias, 0.f);
    }
    atomicAdd(&g_pool[cur * 32 + col], acc);
}

// ---------------- tiny MLP head: [128,32] -> [128,1] ------------------------
__global__ void mlp_kernel(const float* __restrict__ A1, const float* __restrict__ c1,
                           const float* __restrict__ A2, const float* __restrict__ c2,
                           const float* __restrict__ A3, const float* __restrict__ c3,
                           const float* __restrict__ A4, const float* __restrict__ c4,
                           float* __restrict__ out) {
    __shared__ float sA1[32 * 32], sA2[32 * 16], sA3[16 * 8], sA4[8];
    __shared__ float sc1[32], sc2[16], sc3[8];
    int tid = threadIdx.x;  // 128 threads, one per graph
    for (int i = tid; i < 1024; i += 128) sA1[i] = A1[i];
    for (int i = tid; i < 512;  i += 128) sA2[i] = A2[i];
    if (tid < 128) { sA3[tid & 127] = (tid < 128) ? A3[tid] : 0.f; }
    if (tid < 8)  sA4[tid] = A4[tid];
    if (tid < 32) sc1[tid] = c1[tid];
    if (tid < 16) sc2[tid] = c2[tid];
    if (tid < 8)  sc3[tid] = c3[tid];
    __syncthreads();

    float g[32];
#pragma unroll
    for (int i = 0; i < 32; i++) g[i] = g_pool[tid * 32 + i];

    float v1[32];
#pragma unroll
    for (int o = 0; o < 32; o++) {
        float a = sc1[o];
#pragma unroll
        for (int k = 0; k < 32; k++) a += g[k] * sA1[k * 32 + o];
        v1[o] = fmaxf(a, 0.f);
    }
    float v2[16];
#pragma unroll
    for (int o = 0; o < 16; o++) {
        float a = sc2[o];
#pragma unroll
        for (int k = 0; k < 32; k++) a += v1[k] * sA2[k * 16 + o];
        v2[o] = fmaxf(a, 0.f);
    }
    float v3[8];
#pragma unroll
    for (int o = 0; o < 8; o++) {
        float a = sc3[o];
#pragma unroll
        for (int k = 0; k < 16; k++) a += v2[k] * sA3[k * 8 + o];
        v3[o] = fmaxf(a, 0.f);
    }
    float r = __ldg(c4);
#pragma unroll
    for (int k = 0; k < 8; k++) r += v3[k] * sA4[k];
    out[tid] = r;
}

// ---------------- launch ------------------------------------------------------
extern "C" void kernel_launch(void* const* d_in, const int* in_sizes, int n_in,
                              void* d_out, int out_size) {
    const float* x     = (const float*)d_in[0];
    const int*   ei    = (const int*)  d_in[1];
    const int*   batch = (const int*)  d_in[2];
    const float* W1 = (const float*)d_in[3];  const float* b1 = (const float*)d_in[4];
    const float* W2 = (const float*)d_in[5];  const float* b2 = (const float*)d_in[6];
    const float* A1 = (const float*)d_in[7];  const float* c1 = (const float*)d_in[8];
    const float* A2 = (const float*)d_in[9];  const float* c2 = (const float*)d_in[10];
    const float* A3 = (const float*)d_in[11]; const float* c3 = (const float*)d_in[12];
    const float* A4 = (const float*)d_in[13]; const float* c4 = (const float*)d_in[14];
    float* out = (float*)d_out;

    float* h1 = nullptr; float* o1 = nullptr; float* h2 = nullptr; float* o2 = nullptr;
    cudaGetSymbolAddress((void**)&h1, g_h1);
    cudaGetSymbolAddress((void**)&o1, g_o1);
    cudaGetSymbolAddress((void**)&h2, g_h2);
    cudaGetSymbolAddress((void**)&o2, g_o2);

    // degrees + norms
    deg_init_kernel<<<(N_NODES + 255) / 256, 256>>>();
    deg_count_kernel<<<(N_EDGES + 255) / 256, 256>>>(ei);
    dinv_kernel<<<(N_NODES + 255) / 256, 256>>>();

    // layer 1
    xw1_kernel<<<(N_NODES + 31) / 32, 256>>>(x, W1);
    selfloop_init_kernel<16, 4><<<(N_NODES * 16 + 255) / 256, 256>>>(h1, o1);
    scatter_kernel<16, 4><<<((unsigned)N_EDGES * 16 + 255) / 256, 256>>>(ei, h1, o1);

    // layer 2 (bias+relu of layer1 fused into GEMM read)
    xw2_kernel<<<(N_NODES + 31) / 32, 256>>>(W2, b1);
    selfloop_init_kernel<8, 3><<<(N_NODES * 8 + 255) / 256, 256>>>(h2, o2);
    scatter_kernel<8, 3><<<((unsigned)N_EDGES * 8 + 255) / 256, 256>>>(ei, h2, o2);

    // pool (bias+relu of layer2 fused) + MLP head
    pool_zero_kernel<<<(N_GRAPHS * 32 + 255) / 256, 256>>>();
    pool_kernel<<<(N_NODES + 255) / 256, 256>>>(batch, b2);
    mlp_kernel<<<1, 128>>>(A1, c1, A2, c2, A3, c3, A4, c4, out);
}

// round 2
// speedup vs baseline: 1.5557x; 1.5557x over previous
#include <cuda_runtime.h>

#define N_NODES  100000
#define N_EDGES  3200000
#define N_GRAPHS 128
#define SCAN_B   391            // 391*256 = 100096 >= N_NODES

// ---------------- scratch (device globals: no allocations allowed) ----------
__device__ float g_h1[N_NODES * 64];     // (X @ W1) * dinv[row]
__device__ float g_o1[N_NODES * 64];     // aggregated layer 1 (pre-bias/relu)
__device__ float g_h2[N_NODES * 32];     // (relu(o1+b1) @ W2) * dinv[row]
__device__ float g_o2[N_NODES * 32];     // aggregated layer 2 (pre-bias/relu)
__device__ float g_dinv[N_NODES];
__device__ int   g_deg[N_NODES];         // in-degree WITHOUT self loop
__device__ int   g_off[N_NODES + 1];     // CSR offsets (by dst)
__device__ int   g_cursor[N_NODES];
__device__ int   g_bsum[512];
__device__ int   g_csr[N_EDGES];         // src node per CSR slot
__device__ float g_pool[N_GRAPHS * 32];

// ---------------- degree / norm ---------------------------------------------
__global__ void deg_init_kernel() {
    int i = blockIdx.x * blockDim.x + threadIdx.x;
    if (i < N_NODES) g_deg[i] = 0;
}

__global__ void deg_count_kernel(const int* __restrict__ ei) {
    int e = blockIdx.x * blockDim.x + threadIdx.x;
    if (e < N_EDGES) atomicAdd(&g_deg[ei[N_EDGES + e]], 1);
}

__global__ void dinv_kernel() {
    int i = blockIdx.x * blockDim.x + threadIdx.x;
    if (i < N_NODES) g_dinv[i] = rsqrtf((float)(g_deg[i] + 1));  // + self loop
}

// ---------------- 3-kernel exclusive scan of g_deg -> g_off -----------------
__global__ void scan1_kernel() {
    __shared__ int s[256];
    int t = threadIdx.x;
    int i = blockIdx.x * 256 + t;
    int v = (i < N_NODES) ? g_deg[i] : 0;
    s[t] = v; __syncthreads();
#pragma unroll
    for (int o = 1; o < 256; o <<= 1) {
        int a = (t >= o) ? s[t - o] : 0;
        __syncthreads();
        s[t] += a;
        __syncthreads();
    }
    if (i < N_NODES) g_off[i] = s[t] - v;   // exclusive within block
    if (t == 255) g_bsum[blockIdx.x] = s[255];
}

__global__ void scan2_kernel() {            // 1 block x 512 threads
    __shared__ int s[512];
    int t = threadIdx.x;
    int v = (t < SCAN_B) ? g_bsum[t] : 0;
    s[t] = v; __syncthreads();
#pragma unroll
    for (int o = 1; o < 512; o <<= 1) {
        int a = (t >= o) ? s[t - o] : 0;
        __syncthreads();
        s[t] += a;
        __syncthreads();
    }
    if (t < SCAN_B) g_bsum[t] = s[t] - v;   // exclusive block base
    if (t == 511) g_off[N_NODES] = s[511];  // total
}

__global__ void scan3_kernel() {
    int i = blockIdx.x * 256 + threadIdx.x;
    if (i < N_NODES) {
        int o = g_off[i] + g_bsum[blockIdx.x];
        g_off[i] = o;
        g_cursor[i] = o;
    }
}

__global__ void csr_fill_kernel(const int* __restrict__ ei) {
    int e = blockIdx.x * blockDim.x + threadIdx.x;
    if (e < N_EDGES) {
        int src = ei[e];
        int dst = ei[N_EDGES + e];
        int p = atomicAdd(&g_cursor[dst], 1);
        g_csr[p] = src;
    }
}

// ---------------- GEMM 1: h1 = (x @ W1) * dinv[row]  (100000x47 @ 47x64) ----
// Block = 32 rows x 8 col-groups; x tile staged in shared; W read as float4.
__global__ void __launch_bounds__(256) xw1_kernel(const float* __restrict__ x,
                                                  const float* __restrict__ W1) {
    __shared__ float sW[47 * 64];
    __shared__ float sx[32 * 47];
    int tid = threadIdx.x;
    for (int i = tid; i < 47 * 64; i += 256) sW[i] = W1[i];
    int row0 = blockIdx.x * 32;
    for (int i = tid; i < 32 * 47; i += 256) sx[i] = x[row0 * 47 + i];
    __syncthreads();

    int r  = tid >> 3;
    int cg = (tid & 7) * 8;
    const float* xr = sx + r * 47;

    float4 a0 = make_float4(0.f, 0.f, 0.f, 0.f);
    float4 a1 = make_float4(0.f, 0.f, 0.f, 0.f);
#pragma unroll
    for (int k = 0; k < 47; k++) {
        float xv = xr[k];
        float4 w0 = *(const float4*)&sW[k * 64 + cg];
        float4 w1 = *(const float4*)&sW[k * 64 + cg + 4];
        a0.x += xv * w0.x; a0.y += xv * w0.y; a0.z += xv * w0.z; a0.w += xv * w0.w;
        a1.x += xv * w1.x; a1.y += xv * w1.y; a1.z += xv * w1.z; a1.w += xv * w1.w;
    }
    float d = g_dinv[row0 + r];
    a0.x *= d; a0.y *= d; a0.z *= d; a0.w *= d;
    a1.x *= d; a1.y *= d; a1.z *= d; a1.w *= d;
    float4* o = (float4*)(g_h1 + (size_t)(row0 + r) * 64 + cg);
    o[0] = a0; o[1] = a1;
}

// ---------------- GEMM 2: h2 = (relu(o1+b1) @ W2) * dinv  (64 -> 32) --------
__global__ void __launch_bounds__(256) xw2_kernel(const float* __restrict__ W2,
                                                  const float* __restrict__ b1) {
    __shared__ float sW[64 * 32];
    __shared__ float sH[32 * 65];   // padded to kill bank conflicts
    __shared__ float sb[64];
    int tid = threadIdx.x;
    for (int i = tid; i < 64 * 32; i += 256) sW[i] = W2[i];
    if (tid < 64) sb[tid] = b1[tid];
    int row0 = blockIdx.x * 32;
    for (int i = tid; i < 32 * 64; i += 256) sH[(i >> 6) * 65 + (i & 63)] =
        g_o1[(size_t)row0 * 64 + i];
    __syncthreads();

    int r  = tid >> 3;
    int cg = (tid & 7) * 4;
    const float* hr = sH + r * 65;

    float4 a = make_float4(0.f, 0.f, 0.f, 0.f);
#pragma unroll
    for (int k = 0; k < 64; k++) {
        float v = fmaxf(hr[k] + sb[k], 0.f);
        float4 w = *(const float4*)&sW[k * 32 + cg];
        a.x += v * w.x; a.y += v * w.y; a.z += v * w.z; a.w += v * w.w;
    }
    float d = g_dinv[row0 + r];
    a.x *= d; a.y *= d; a.z *= d; a.w *= d;
    *(float4*)(g_h2 + (size_t)(row0 + r) * 32 + cg) = a;
}

// ---------------- CSR gather: o[n] = dinv[n] * (hs[n] + sum_src hs[src]) ----
// LANES = 1<<LOG2L threads per node, each lane owns one float4 column chunk.
template <int LOG2L>
__global__ void __launch_bounds__(256) gather_kernel(const float* __restrict__ hs,
                                                     float* __restrict__ o) {
    unsigned t = blockIdx.x * blockDim.x + threadIdx.x;
    unsigned node = t >> LOG2L;
    if (node >= N_NODES) return;
    unsigned lane = t & ((1u << LOG2L) - 1u);

    int s0 = __ldg(&g_off[node]);
    int s1 = __ldg(&g_off[node + 1]);
    const float4* H = (const float4*)hs;

    float4 acc = __ldg(&H[((size_t)node << LOG2L) + lane]);  // self term
    float4 acc2 = make_float4(0.f, 0.f, 0.f, 0.f);

    int j = s0;
    for (; j + 1 < s1; j += 2) {
        int sA = __ldg(&g_csr[j]);
        int sB = __ldg(&g_csr[j + 1]);
        float4 vA = __ldg(&H[((size_t)sA << LOG2L) + lane]);
        float4 vB = __ldg(&H[((size_t)sB << LOG2L) + lane]);
        acc.x += vA.x; acc.y += vA.y; acc.z += vA.z; acc.w += vA.w;
        acc2.x += vB.x; acc2.y += vB.y; acc2.z += vB.z; acc2.w += vB.w;
    }
    if (j < s1) {
        int sA = __ldg(&g_csr[j]);
        float4 vA = __ldg(&H[((size_t)sA << LOG2L) + lane]);
        acc.x += vA.x; acc.y += vA.y; acc.z += vA.z; acc.w += vA.w;
    }
    float dd = g_dinv[node];
    acc.x = (acc.x + acc2.x) * dd;
    acc.y = (acc.y + acc2.y) * dd;
    acc.z = (acc.z + acc2.z) * dd;
    acc.w = (acc.w + acc2.w) * dd;
    ((float4*)o)[((size_t)node << LOG2L) + lane] = acc;
}

// ---------------- pooling: g[batch[n]] += relu(o2[n] + b2) ------------------
__global__ void pool_zero_kernel() {
    int i = blockIdx.x * blockDim.x + threadIdx.x;
    if (i < N_GRAPHS * 32) g_pool[i] = 0.f;
}

__global__ void pool_kernel(const int* __restrict__ batch, const float* __restrict__ b2) {
    unsigned t = blockIdx.x * blockDim.x + threadIdx.x;
    int col   = t & 31;
    int chunk = t >> 5;
    int n0 = chunk * 32;
    if (n0 >= N_NODES) return;
    int n1 = min(n0 + 32, N_NODES);
    float bias = __ldg(b2 + col);
    float acc = 0.f;
    int cur = __ldg(batch + n0);
    for (int n = n0; n < n1; n++) {
        int b = __ldg(batch + n);
        if (b != cur) {
            atomicAdd(&g_pool[cur * 32 + col], acc);
            acc = 0.f;
            cur = b;
        }
        acc += fmaxf(g_o2[(size_t)n * 32 + col] + bias, 0.f);
    }
    atomicAdd(&g_pool[cur * 32 + col], acc);
}

// ---------------- tiny MLP head: [128,32] -> [128,1] ------------------------
__global__ void mlp_kernel(const float* __restrict__ A1, const float* __restrict__ c1,
                           const float* __restrict__ A2, const float* __restrict__ c2,
                           const float* __restrict__ A3, const float* __restrict__ c3,
                           const float* __restrict__ A4, const float* __restrict__ c4,
                           float* __restrict__ out) {
    __shared__ float sA1[32 * 32], sA2[32 * 16], sA3[16 * 8], sA4[8];
    __shared__ float sc1[32], sc2[16], sc3[8];
    int tid = threadIdx.x;  // 128 threads, one per graph
    for (int i = tid; i < 1024; i += 128) sA1[i] = A1[i];
    for (int i = tid; i < 512;  i += 128) sA2[i] = A2[i];
    if (tid < 128) sA3[tid] = A3[tid];
    if (tid < 8)  sA4[tid] = A4[tid];
    if (tid < 32) sc1[tid] = c1[tid];
    if (tid < 16) sc2[tid] = c2[tid];
    if (tid < 8)  sc3[tid] = c3[tid];
    __syncthreads();

    float g[32];
#pragma unroll
    for (int i = 0; i < 32; i++) g[i] = g_pool[tid * 32 + i];

    float v1[32];
#pragma unroll
    for (int o = 0; o < 32; o++) {
        float a = sc1[o];
#pragma unroll
        for (int k = 0; k < 32; k++) a += g[k] * sA1[k * 32 + o];
        v1[o] = fmaxf(a, 0.f);
    }
    float v2[16];
#pragma unroll
    for (int o = 0; o < 16; o++) {
        float a = sc2[o];
#pragma unroll
        for (int k = 0; k < 32; k++) a += v1[k] * sA2[k * 16 + o];
        v2[o] = fmaxf(a, 0.f);
    }
    float v3[8];
#pragma unroll
    for (int o = 0; o < 8; o++) {
        float a = sc3[o];
#pragma unroll
        for (int k = 0; k < 16; k++) a += v2[k] * sA3[k * 8 + o];
        v3[o] = fmaxf(a, 0.f);
    }
    float r = __ldg(c4);
#pragma unroll
    for (int k = 0; k < 8; k++) r += v3[k] * sA4[k];
    out[tid] = r;
}

// ---------------- launch -----------------------------------------------------
extern "C" void kernel_launch(void* const* d_in, const int* in_sizes, int n_in,
                              void* d_out, int out_size) {
    const float* x     = (const float*)d_in[0];
    const int*   ei    = (const int*)  d_in[1];
    const int*   batch = (const int*)  d_in[2];
    const float* W1 = (const float*)d_in[3];  const float* b1 = (const float*)d_in[4];
    const float* W2 = (const float*)d_in[5];  const float* b2 = (const float*)d_in[6];
    const float* A1 = (const float*)d_in[7];  const float* c1 = (const float*)d_in[8];
    const float* A2 = (const float*)d_in[9];  const float* c2 = (const float*)d_in[10];
    const float* A3 = (const float*)d_in[11]; const float* c3 = (const float*)d_in[12];
    const float* A4 = (const float*)d_in[13]; const float* c4 = (const float*)d_in[14];
    float* out = (float*)d_out;

    float* h1 = nullptr; float* o1 = nullptr; float* h2 = nullptr; float* o2 = nullptr;
    cudaGetSymbolAddress((void**)&h1, g_h1);
    cudaGetSymbolAddress((void**)&o1, g_o1);
    cudaGetSymbolAddress((void**)&h2, g_h2);
    cudaGetSymbolAddress((void**)&o2, g_o2);

    // degree + norms + CSR-by-dst build
    deg_init_kernel<<<SCAN_B, 256>>>();
    deg_count_kernel<<<(N_EDGES + 255) / 256, 256>>>(ei);
    dinv_kernel<<<SCAN_B, 256>>>();
    scan1_kernel<<<SCAN_B, 256>>>();
    scan2_kernel<<<1, 512>>>();
    scan3_kernel<<<SCAN_B, 256>>>();
    csr_fill_kernel<<<(N_EDGES + 255) / 256, 256>>>(ei);

    // layer 1: GEMM (pre-scaled by dinv) + CSR gather
    xw1_kernel<<<N_NODES / 32, 256>>>(x, W1);
    gather_kernel<4><<<(N_NODES * 16 + 255) / 256, 256>>>(h1, o1);

    // layer 2
    xw2_kernel<<<N_NODES / 32, 256>>>(W2, b1);
    gather_kernel<3><<<(N_NODES * 8 + 255) / 256, 256>>>(h2, o2);

    // pool (bias+relu fused) + MLP head
    pool_zero_kernel<<<(N_GRAPHS * 32 + 255) / 256, 256>>>();
    pool_kernel<<<(N_NODES + 255) / 256, 256>>>(batch, b2);
    mlp_kernel<<<1, 128>>>(A1, c1, A2, c2, A3, c3, A4, c4, out);
}

// round 3
// speedup vs baseline: 1.6346x; 1.0507x over previous
#include <cuda_runtime.h>
#include <cuda_fp16.h>

#define N_NODES  100000
#define N_EDGES  3200000
#define N_GRAPHS 128
#define SCAN_B   391            // 391*256 = 100096 >= N_NODES

// ---------------- scratch (device globals: no allocations allowed) ----------
__device__ __half g_h1[N_NODES * 64];    // (X @ W1) * dinv[row], fp16
__device__ float  g_o1[N_NODES * 64];    // aggregated layer 1 (pre-bias/relu)
__device__ __half g_h2[N_NODES * 32];    // (relu(o1+b1) @ W2) * dinv[row], fp16
__device__ float  g_o2[N_NODES * 32];    // aggregated layer 2 (pre-bias/relu)
__device__ float  g_dinv[N_NODES];
__device__ int    g_deg[N_NODES];        // in-degree WITHOUT self loop
__device__ int    g_off[N_NODES + 1];    // CSR offsets (by dst)
__device__ int    g_cursor[N_NODES];
__device__ int    g_bsum[512];
__device__ int    g_csr[N_EDGES];        // src node per CSR slot
__device__ float  g_pool[N_GRAPHS * 32];

union HU4 { uint4 u; __half2 h[4]; };

// ---------------- degree ----------------------------------------------------
__global__ void deg_init_kernel() {
    int i = blockIdx.x * blockDim.x + threadIdx.x;
    if (i < N_NODES) g_deg[i] = 0;
}

__global__ void deg_count_kernel(const int* __restrict__ ei) {
    int e = blockIdx.x * blockDim.x + threadIdx.x;
    if (e < N_EDGES) atomicAdd(&g_deg[ei[N_EDGES + e]], 1);
}

// ---------------- scan (+ fused dinv) ----------------------------------------
__global__ void scan1_kernel() {
    __shared__ int s[256];
    int t = threadIdx.x;
    int i = blockIdx.x * 256 + t;
    int v = (i < N_NODES) ? g_deg[i] : 0;
    if (i < N_NODES) g_dinv[i] = rsqrtf((float)(v + 1));   // fused norm
    s[t] = v; __syncthreads();
#pragma unroll
    for (int o = 1; o < 256; o <<= 1) {
        int a = (t >= o) ? s[t - o] : 0;
        __syncthreads();
        s[t] += a;
        __syncthreads();
    }
    if (i < N_NODES) g_off[i] = s[t] - v;   // exclusive within block
    if (t == 255) g_bsum[blockIdx.x] = s[255];
}

__global__ void scan2_kernel() {            // 1 block x 512 threads
    __shared__ int s[512];
    int t = threadIdx.x;
    int v = (t < SCAN_B) ? g_bsum[t] : 0;
    s[t] = v; __syncthreads();
#pragma unroll
    for (int o = 1; o < 512; o <<= 1) {
        int a = (t >= o) ? s[t - o] : 0;
        __syncthreads();
        s[t] += a;
        __syncthreads();
    }
    if (t < SCAN_B) g_bsum[t] = s[t] - v;   // exclusive block base
    if (t == 511) g_off[N_NODES] = s[511];
}

__global__ void scan3_kernel() {
    int i = blockIdx.x * 256 + threadIdx.x;
    if (i < N_NODES) {
        int o = g_off[i] + g_bsum[blockIdx.x];
        g_off[i] = o;
        g_cursor[i] = o;
    }
}

__global__ void csr_fill_kernel(const int* __restrict__ ei) {
    int e = blockIdx.x * blockDim.x + threadIdx.x;
    if (e < N_EDGES) {
        int src = ei[e];
        int dst = ei[N_EDGES + e];
        int p = atomicAdd(&g_cursor[dst], 1);
        g_csr[p] = src;
    }
}

// ---------------- GEMM 1: h1 = fp16((x @ W1) * dinv[row]) -------------------
__global__ void __launch_bounds__(256) xw1_kernel(const float* __restrict__ x,
                                                  const float* __restrict__ W1) {
    __shared__ float sW[47 * 64];
    __shared__ float sx[32 * 47];
    int tid = threadIdx.x;
    for (int i = tid; i < 47 * 64; i += 256) sW[i] = W1[i];
    int row0 = blockIdx.x * 32;
    for (int i = tid; i < 32 * 47; i += 256) sx[i] = x[row0 * 47 + i];
    __syncthreads();

    int r  = tid >> 3;
    int cg = (tid & 7) * 8;
    const float* xr = sx + r * 47;

    float4 a0 = make_float4(0.f, 0.f, 0.f, 0.f);
    float4 a1 = make_float4(0.f, 0.f, 0.f, 0.f);
#pragma unroll
    for (int k = 0; k < 47; k++) {
        float xv = xr[k];
        float4 w0 = *(const float4*)&sW[k * 64 + cg];
        float4 w1 = *(const float4*)&sW[k * 64 + cg + 4];
        a0.x += xv * w0.x; a0.y += xv * w0.y; a0.z += xv * w0.z; a0.w += xv * w0.w;
        a1.x += xv * w1.x; a1.y += xv * w1.y; a1.z += xv * w1.z; a1.w += xv * w1.w;
    }
    float d = g_dinv[row0 + r];
    HU4 o;
    o.h[0] = __float22half2_rn(make_float2(a0.x * d, a0.y * d));
    o.h[1] = __float22half2_rn(make_float2(a0.z * d, a0.w * d));
    o.h[2] = __float22half2_rn(make_float2(a1.x * d, a1.y * d));
    o.h[3] = __float22half2_rn(make_float2(a1.z * d, a1.w * d));
    *(uint4*)(g_h1 + (size_t)(row0 + r) * 64 + cg) = o.u;
}

// ---------------- GEMM 2: h2 = fp16((relu(o1+b1) @ W2) * dinv) --------------
__global__ void __launch_bounds__(256) xw2_kernel(const float* __restrict__ W2,
                                                  const float* __restrict__ b1) {
    __shared__ float sW[64 * 32];
    __shared__ float sH[32 * 65];   // padded to kill bank conflicts
    __shared__ float sb[64];
    int tid = threadIdx.x;
    for (int i = tid; i < 64 * 32; i += 256) sW[i] = W2[i];
    if (tid < 64) sb[tid] = b1[tid];
    int row0 = blockIdx.x * 32;
    for (int i = tid; i < 32 * 64; i += 256) sH[(i >> 6) * 65 + (i & 63)] =
        g_o1[(size_t)row0 * 64 + i];
    __syncthreads();

    int r  = tid >> 3;
    int cg = (tid & 7) * 4;
    const float* hr = sH + r * 65;

    float4 a = make_float4(0.f, 0.f, 0.f, 0.f);
#pragma unroll
    for (int k = 0; k < 64; k++) {
        float v = fmaxf(hr[k] + sb[k], 0.f);
        float4 w = *(const float4*)&sW[k * 32 + cg];
        a.x += v * w.x; a.y += v * w.y; a.z += v * w.z; a.w += v * w.w;
    }
    float d = g_dinv[row0 + r];
    __half2 p0 = __float22half2_rn(make_float2(a.x * d, a.y * d));
    __half2 p1 = __float22half2_rn(make_float2(a.z * d, a.w * d));
    uint2 u = make_uint2(*(unsigned*)&p0, *(unsigned*)&p1);
    *(uint2*)(g_h2 + (size_t)(row0 + r) * 32 + cg) = u;
}

// ---------------- CSR gather (fp16 in, fp32 out) ----------------------------
// LANES = 1<<LOG2L threads per node; each lane owns 8 halves (one uint4).
template <int LOG2L>
__global__ void __launch_bounds__(256) gather_kernel(const __half* __restrict__ hs,
                                                     float* __restrict__ o) {
    unsigned t = blockIdx.x * blockDim.x + threadIdx.x;
    unsigned node = t >> LOG2L;
    if (node >= N_NODES) return;
    unsigned lane = t & ((1u << LOG2L) - 1u);

    int s0 = __ldg(&g_off[node]);
    int s1 = __ldg(&g_off[node + 1]);
    const uint4* H = (const uint4*)hs;
    unsigned base = (node << LOG2L) + lane;

    HU4 self; self.u = __ldg(&H[base]);
    float2 a0 = __half22float2(self.h[0]);
    float2 a1 = __half22float2(self.h[1]);
    float2 a2 = __half22float2(self.h[2]);
    float2 a3 = __half22float2(self.h[3]);
    float2 b0 = make_float2(0.f, 0.f), b1 = make_float2(0.f, 0.f);
    float2 b2 = make_float2(0.f, 0.f), b3 = make_float2(0.f, 0.f);

    int j = s0;
    for (; j + 1 < s1; j += 2) {
        int sA = __ldg(&g_csr[j]);
        int sB = __ldg(&g_csr[j + 1]);
        HU4 vA; vA.u = __ldg(&H[((size_t)sA << LOG2L) + lane]);
        HU4 vB; vB.u = __ldg(&H[((size_t)sB << LOG2L) + lane]);
        float2 f;
        f = __half22float2(vA.h[0]); a0.x += f.x; a0.y += f.y;
        f = __half22float2(vA.h[1]); a1.x += f.x; a1.y += f.y;
        f = __half22float2(vA.h[2]); a2.x += f.x; a2.y += f.y;
        f = __half22float2(vA.h[3]); a3.x += f.x; a3.y += f.y;
        f = __half22float2(vB.h[0]); b0.x += f.x; b0.y += f.y;
        f = __half22float2(vB.h[1]); b1.x += f.x; b1.y += f.y;
        f = __half22float2(vB.h[2]); b2.x += f.x; b2.y += f.y;
        f = __half22float2(vB.h[3]); b3.x += f.x; b3.y += f.y;
    }
    if (j < s1) {
        int sA = __ldg(&g_csr[j]);
        HU4 vA; vA.u = __ldg(&H[((size_t)sA << LOG2L) + lane]);
        float2 f;
        f = __half22float2(vA.h[0]); a0.x += f.x; a0.y += f.y;
        f = __half22float2(vA.h[1]); a1.x += f.x; a1.y += f.y;
        f = __half22float2(vA.h[2]); a2.x += f.x; a2.y += f.y;
        f = __half22float2(vA.h[3]); a3.x += f.x; a3.y += f.y;
    }
    float dd = g_dinv[node];
    float4 o0 = make_float4((a0.x + b0.x) * dd, (a0.y + b0.y) * dd,
                            (a1.x + b1.x) * dd, (a1.y + b1.y) * dd);
    float4 o1v = make_float4((a2.x + b2.x) * dd, (a2.y + b2.y) * dd,
                             (a3.x + b3.x) * dd, (a3.y + b3.y) * dd);
    float4* op = (float4*)(o + (size_t)base * 8);
    op[0] = o0; op[1] = o1v;
}

// ---------------- pooling: g[batch[n]] += relu(o2[n] + b2) ------------------
__global__ void pool_zero_kernel() {
    int i = blockIdx.x * blockDim.x + threadIdx.x;
    if (i < N_GRAPHS * 32) g_pool[i] = 0.f;
}

__global__ void pool_kernel(const int* __restrict__ batch, const float* __restrict__ b2) {
    unsigned t = blockIdx.x * blockDim.x + threadIdx.x;
    int col   = t & 31;
    int chunk = t >> 5;
    int n0 = chunk * 32;
    if (n0 >= N_NODES) return;
    int n1 = min(n0 + 32, N_NODES);
    float bias = __ldg(b2 + col);
    float acc = 0.f;
    int cur = __ldg(batch + n0);
    for (int n = n0; n < n1; n++) {
        int b = __ldg(batch + n);
        if (b != cur) {
            atomicAdd(&g_pool[cur * 32 + col], acc);
            acc = 0.f;
            cur = b;
        }
        acc += fmaxf(g_o2[(size_t)n * 32 + col] + bias, 0.f);
    }
    atomicAdd(&g_pool[cur * 32 + col], acc);
}

// ---------------- tiny MLP head: [128,32] -> [128,1] ------------------------
__global__ void mlp_kernel(const float* __restrict__ A1, const float* __restrict__ c1,
                           const float* __restrict__ A2, const float* __restrict__ c2,
                           const float* __restrict__ A3, const float* __restrict__ c3,
                           const float* __restrict__ A4, const float* __restrict__ c4,
                           float* __restrict__ out) {
    __shared__ float sA1[32 * 32], sA2[32 * 16], sA3[16 * 8], sA4[8];
    __shared__ float sc1[32], sc2[16], sc3[8];
    int tid = threadIdx.x;  // 128 threads, one per graph
    for (int i = tid; i < 1024; i += 128) sA1[i] = A1[i];
    for (int i = tid; i < 512;  i += 128) sA2[i] = A2[i];
    if (tid < 128) sA3[tid] = A3[tid];
    if (tid < 8)  sA4[tid] = A4[tid];
    if (tid < 32) sc1[tid] = c1[tid];
    if (tid < 16) sc2[tid] = c2[tid];
    if (tid < 8)  sc3[tid] = c3[tid];
    __syncthreads();

    float g[32];
#pragma unroll
    for (int i = 0; i < 32; i++) g[i] = g_pool[tid * 32 + i];

    float v1[32];
#pragma unroll
    for (int o = 0; o < 32; o++) {
        float a = sc1[o];
#pragma unroll
        for (int k = 0; k < 32; k++) a += g[k] * sA1[k * 32 + o];
        v1[o] = fmaxf(a, 0.f);
    }
    float v2[16];
#pragma unroll
    for (int o = 0; o < 16; o++) {
        float a = sc2[o];
#pragma unroll
        for (int k = 0; k < 32; k++) a += v1[k] * sA2[k * 16 + o];
        v2[o] = fmaxf(a, 0.f);
    }
    float v3[8];
#pragma unroll
    for (int o = 0; o < 8; o++) {
        float a = sc3[o];
#pragma unroll
        for (int k = 0; k < 16; k++) a += v2[k] * sA3[k * 8 + o];
        v3[o] = fmaxf(a, 0.f);
    }
    float r = __ldg(c4);
#pragma unroll
    for (int k = 0; k < 8; k++) r += v3[k] * sA4[k];
    out[tid] = r;
}

// ---------------- launch -----------------------------------------------------
extern "C" void kernel_launch(void* const* d_in, const int* in_sizes, int n_in,
                              void* d_out, int out_size) {
    const float* x     = (const float*)d_in[0];
    const int*   ei    = (const int*)  d_in[1];
    const int*   batch = (const int*)  d_in[2];
    const float* W1 = (const float*)d_in[3];  const float* b1 = (const float*)d_in[4];
    const float* W2 = (const float*)d_in[5];  const float* b2 = (const float*)d_in[6];
    const float* A1 = (const float*)d_in[7];  const float* c1 = (const float*)d_in[8];
    const float* A2 = (const float*)d_in[9];  const float* c2 = (const float*)d_in[10];
    const float* A3 = (const float*)d_in[11]; const float* c3 = (const float*)d_in[12];
    const float* A4 = (const float*)d_in[13]; const float* c4 = (const float*)d_in[14];
    float* out = (float*)d_out;

    __half* h1 = nullptr; float* o1 = nullptr; __half* h2 = nullptr; float* o2 = nullptr;
    cudaGetSymbolAddress((void**)&h1, g_h1);
    cudaGetSymbolAddress((void**)&o1, g_o1);
    cudaGetSymbolAddress((void**)&h2, g_h2);
    cudaGetSymbolAddress((void**)&o2, g_o2);

    // degree + norms + CSR-by-dst build
    deg_init_kernel<<<SCAN_B, 256>>>();
    deg_count_kernel<<<(N_EDGES + 255) / 256, 256>>>(ei);
    scan1_kernel<<<SCAN_B, 256>>>();     // also computes dinv
    scan2_kernel<<<1, 512>>>();
    scan3_kernel<<<SCAN_B, 256>>>();
    csr_fill_kernel<<<(N_EDGES + 255) / 256, 256>>>(ei);

    // layer 1: GEMM (pre-scaled by dinv, fp16 out) + CSR gather
    xw1_kernel<<<N_NODES / 32, 256>>>(x, W1);
    gather_kernel<3><<<(N_NODES * 8 + 255) / 256, 256>>>(h1, o1);

    // layer 2
    xw2_kernel<<<N_NODES / 32, 256>>>(W2, b1);
    gather_kernel<2><<<(N_NODES * 4 + 255) / 256, 256>>>(h2, o2);

    // pool (bias+relu fused) + MLP head
    pool_zero_kernel<<<(N_GRAPHS * 32 + 255) / 256, 256>>>();
    pool_kernel<<<(N_NODES + 255) / 256, 256>>>(batch, b2);
    mlp_kernel<<<1, 128>>>(A1, c1, A2, c2, A3, c3, A4, c4, out);
}